// round 12
// baseline (speedup 1.0000x reference)
#include <cuda_runtime.h>
#include <math.h>

// HorizonReward — 2-warp producer/consumer with named split barriers.
// W1 owns the u-cycle entirely in registers (dyn+means+policy); W0 owns the
// S-cycle (dyn+moments+chol+reward) and publishes S via ONE STS (lanes 0-9).
// bar.arrive/bar.sync pairs (ids 1,2), double-buffered smem. Numerics =
// verified R10/R11 scheme (uncentered moments, analytic linear-coordinate
// covariance, x5-prescaled chol, packed 16-lane policy + radix-4 reduce).

typedef unsigned long long u64;

__device__ __forceinline__ u64 pk(float lo, float hi) {
    u64 r; asm("mov.b64 %0,{%1,%2};" : "=l"(r) : "f"(lo), "f"(hi)); return r;
}
__device__ __forceinline__ void upk(u64 a, float& x, float& y) {
    asm("mov.b64 {%0,%1},%2;" : "=f"(x), "=f"(y) : "l"(a));
}
__device__ __forceinline__ u64 sp2(float s) { return pk(s, s); }
__device__ __forceinline__ u64 fma2_(u64 a, u64 b, u64 c) {
    u64 d; asm("fma.rn.f32x2 %0,%1,%2,%3;" : "=l"(d) : "l"(a), "l"(b), "l"(c)); return d;
}
__device__ __forceinline__ u64 mul2_(u64 a, u64 b) {
    u64 d; asm("mul.rn.f32x2 %0,%1,%2;" : "=l"(d) : "l"(a), "l"(b)); return d;
}
__device__ __forceinline__ u64 add2_(u64 a, u64 b) {
    u64 d; asm("add.rn.f32x2 %0,%1,%2;" : "=l"(d) : "l"(a), "l"(b)); return d;
}
__device__ __forceinline__ float rcp_(float x) {
    float r; asm("rcp.approx.f32 %0,%1;" : "=f"(r) : "f"(x)); return r;
}
__device__ __forceinline__ float ex2_(float x) {
    float r; asm("ex2.approx.f32 %0,%1;" : "=f"(r) : "f"(x)); return r;
}
__device__ __forceinline__ float red16_r4(float x) {
    const float a = __shfl_xor_sync(0xffffffffu, x, 4);
    const float b = __shfl_xor_sync(0xffffffffu, x, 8);
    const float c = __shfl_xor_sync(0xffffffffu, x, 12);
    x = (x + a) + (b + c);
    const float d = __shfl_xor_sync(0xffffffffu, x, 1);
    const float e = __shfl_xor_sync(0xffffffffu, x, 2);
    const float f = __shfl_xor_sync(0xffffffffu, x, 3);
    return (x + d) + (e + f);
}

#define BAR_ARRIVE_1() asm volatile("bar.arrive 1, 64;" ::: "memory")
#define BAR_SYNC_1()   asm volatile("bar.sync 1, 64;"   ::: "memory")
#define BAR_ARRIVE_2() asm volatile("bar.arrive 2, 64;" ::: "memory")
#define BAR_SYNC_2()   asm volatile("bar.sync 2, 64;"   ::: "memory")

#define DTc      0.05f
#define K1c      (0.05f / 1.1f)
#define K3c      (0.5f * (4.0f / 3.0f))
#define K2c      (0.5f * 0.1f / 1.1f)
#define INV11c   (1.0f / 1.1f)
#define DIAG5c   (5.0f * (0.01f * 0.05f + 2.0f * 1e-6f))

__global__ __launch_bounds__(64, 1)
void horizon_reward_kernel(const float* __restrict__ p, float* __restrict__ out)
{
    const int tid = threadIdx.x;
    const int wid = tid >> 5;
    const int lane = tid & 31;
    const int jj = lane & 15;

    __shared__ float sm_u[2];
    __shared__ float sm_S[2][12];   // slots 0..9 = S entries, 10 = 0.0f

    // ---- sigma-point roles ----
    const int pt = jj;
    const int col = (pt == 0) ? 3 : ((pt - 1) & 3);
    const float sgn = (pt >= 1 && pt <= 4) ? 1.f : ((pt >= 5 && pt <= 8) ? -1.f : 0.f);
    const bool isC0 = (col == 0), isC1 = (col == 1), isC2 = (col == 2);
    // smem S slot indices for this lane's r1/r2/r3 (slot 10 = 0)
    const int i1 = isC0 ? 1 : (isC1 ? 4 : 10);
    const int i2 = isC0 ? 2 : (isC1 ? 5 : (isC2 ? 7 : 10));
    const int i3 = isC0 ? 3 : (isC1 ? 6 : (isC2 ? 8 : 9));

    const u64 NL2E2 = sp2(-1.4426950408889634f);
    const u64 NM1_2 = sp2(-1.f);
    const u64 W0_2 = sp2(0.2f), WI_2 = sp2(0.1f), HALF2 = sp2(0.5f);

    // ---- state ----
    float m0 = 0.f, m1 = 0.f, m2 = 0.1f, m3 = 0.f;
    const float r0i = 2.23606797749979f * 1e-3f;
    float S00 = r0i, S10 = 0.f, S20 = 0.f, S30 = 0.f;
    float S11 = r0i, S21 = 0.f, S31 = 0.f;
    float S22 = r0i, S32 = 0.f;
    float S33 = r0i;

    // dynamics prep registers (both warps)
    float r0_, r1_, r3_, tks_, g98_, c_, rd_;
    {
        r0_ = sgn * (isC0 ? S00 : 0.f);
        r1_ = sgn * (isC0 ? S10 : (isC1 ? S11 : 0.f));
        const float r2 = sgn * (isC0 ? S20 : (isC1 ? S21 : (isC2 ? S22 : 0.f)));
        r3_ = sgn * (isC0 ? S30 : (isC1 ? S31 : (isC2 ? S32 : S33)));
        const float th = m2 + r2, thd = m3 + r3_;
        const float s = __sinf(th);
        c_ = __cosf(th);
        rd_ = rcp_(fmaf(-K2c * c_, c_, K3c));
        tks_ = ((thd * thd) * K1c) * s;
        g98_ = 9.8f * s;
    }

    float reward = 0.f;
    float u_reg = 0.f;

    if (wid == 1) {
        // ---- W1: policy params + initial u ----
        u64 nmuA[4], LA[10], nmuB[4], LB[10];
        float wA0, wA1, wB0, wB1;
        {
            const int a0 = jj, a1 = jj + 16, b0 = jj + 32, b1 = jj + 48;
            const bool hb1 = (b1 < 50);
            wA0 = p[a0]; wA1 = p[a1];
            wB0 = p[b0]; wB1 = hb1 ? p[b1] : 0.f;
            #pragma unroll
            for (int k = 0; k < 4; ++k) {
                nmuA[k] = pk(-p[50 + k * 50 + a0], -p[50 + k * 50 + a1]);
                nmuB[k] = pk(-p[50 + k * 50 + b0], hb1 ? -p[50 + k * 50 + b1] : 0.f);
            }
            #pragma unroll
            for (int t = 0; t < 10; ++t) {
                LA[t] = pk(p[250 + a0 * 10 + t], p[250 + a1 * 10 + t]);
                LB[t] = pk(p[250 + b0 * 10 + t], hb1 ? p[250 + b1 * 10 + t] : 0.f);
            }
        }

        // initial u_0 = policy(m_0)
        {
            u64 d0 = add2_(sp2(m0), nmuA[0]), d1 = add2_(sp2(m1), nmuA[1]);
            u64 d2 = add2_(sp2(m2), nmuA[2]), d3 = add2_(sp2(m3), nmuA[3]);
            u64 l0 = mul2_(LA[0], d0);
            l0 = fma2_(LA[4], d1, l0); l0 = fma2_(LA[5], d2, l0); l0 = fma2_(LA[7], d3, l0);
            u64 l1 = mul2_(LA[1], d1); l1 = fma2_(LA[6], d2, l1); l1 = fma2_(LA[8], d3, l1);
            u64 l2 = mul2_(LA[2], d2); l2 = fma2_(LA[9], d3, l2);
            u64 l3 = mul2_(LA[3], d3);
            u64 qA = fma2_(l1, l1, mul2_(l0, l0));
            qA = add2_(qA, fma2_(l3, l3, mul2_(l2, l2)));
            qA = mul2_(qA, NL2E2);
            d0 = add2_(sp2(m0), nmuB[0]); d1 = add2_(sp2(m1), nmuB[1]);
            d2 = add2_(sp2(m2), nmuB[2]); d3 = add2_(sp2(m3), nmuB[3]);
            l0 = mul2_(LB[0], d0);
            l0 = fma2_(LB[4], d1, l0); l0 = fma2_(LB[5], d2, l0); l0 = fma2_(LB[7], d3, l0);
            l1 = mul2_(LB[1], d1); l1 = fma2_(LB[6], d2, l1); l1 = fma2_(LB[8], d3, l1);
            l2 = mul2_(LB[2], d2); l2 = fma2_(LB[9], d3, l2);
            l3 = mul2_(LB[3], d3);
            u64 qB = fma2_(l1, l1, mul2_(l0, l0));
            qB = add2_(qB, fma2_(l3, l3, mul2_(l2, l2)));
            qB = mul2_(qB, NL2E2);
            float qa0, qa1, qb0, qb1;
            upk(qA, qa0, qa1); upk(qB, qb0, qb1);
            float acc = fmaf(wA0, ex2_(qa0), wA1 * ex2_(qa1))
                      + fmaf(wB0, ex2_(qb0), wB1 * ex2_(qb1));
            acc = red16_r4(acc);
            u_reg = fminf(fmaxf(acc, -10.f), 10.f);
        }
        if (lane == 0) sm_u[0] = u_reg;
        BAR_ARRIVE_1();

        // ================= W1 loop: u-cycle =================
        #pragma unroll 1
        for (int t = 0; t < 60; ++t) {
            // dynamics with u_reg (= u_t) and local prep
            const float ud = u_reg * INV11c;
            const float temp = tks_ + ud;
            const float num = fmaf(-c_, temp, g98_);
            const float ta = num * rd_;
            const float xa = fmaf(-K1c, ta * c_, temp);
            const float y1 = fmaf(DTc, xa, r1_);
            const float y3 = fmaf(DTc, ta, r3_);

            // gather + means
            u64 z1_4 = 0, z5_8 = 0, z0;
            {
                const float g10 = __shfl_sync(0xffffffffu, y1, 0);
                const float g30 = __shfl_sync(0xffffffffu, y3, 0);
                z0 = pk(g10, g30);
                u64 zz[8];
                #pragma unroll
                for (int j = 1; j < 9; ++j) {
                    const float g1 = __shfl_sync(0xffffffffu, y1, j);
                    const float g3 = __shfl_sync(0xffffffffu, y3, j);
                    zz[j - 1] = pk(g1, g3);
                }
                z1_4 = add2_(add2_(zz[0], zz[1]), add2_(zz[2], zz[3]));
                z5_8 = add2_(add2_(zz[4], zz[5]), add2_(zz[6], zz[7]));
            }
            const u64 d13 = fma2_(WI_2, add2_(z1_4, z5_8), mul2_(W0_2, z0));
            float d1, d3; upk(d13, d1, d3);

            const float n0 = fmaf(DTc, m1, m0);
            const float n2 = fmaf(DTc, m3, m2);
            const float n1 = m1 + d1;
            const float n3 = m3 + d3;

            // policy(n) -> u_{t+1}
            u64 d0 = add2_(sp2(n0), nmuA[0]), dd1 = add2_(sp2(n1), nmuA[1]);
            u64 d2 = add2_(sp2(n2), nmuA[2]), dd3 = add2_(sp2(n3), nmuA[3]);
            u64 l0 = mul2_(LA[0], d0);
            l0 = fma2_(LA[4], dd1, l0); l0 = fma2_(LA[5], d2, l0); l0 = fma2_(LA[7], dd3, l0);
            u64 l1 = mul2_(LA[1], dd1); l1 = fma2_(LA[6], d2, l1); l1 = fma2_(LA[8], dd3, l1);
            u64 l2 = mul2_(LA[2], d2); l2 = fma2_(LA[9], dd3, l2);
            u64 l3 = mul2_(LA[3], dd3);
            u64 qA = fma2_(l1, l1, mul2_(l0, l0));
            qA = add2_(qA, fma2_(l3, l3, mul2_(l2, l2)));
            qA = mul2_(qA, NL2E2);
            d0 = add2_(sp2(n0), nmuB[0]); dd1 = add2_(sp2(n1), nmuB[1]);
            d2 = add2_(sp2(n2), nmuB[2]); dd3 = add2_(sp2(n3), nmuB[3]);
            l0 = mul2_(LB[0], d0);
            l0 = fma2_(LB[4], dd1, l0); l0 = fma2_(LB[5], d2, l0); l0 = fma2_(LB[7], dd3, l0);
            l1 = mul2_(LB[1], dd1); l1 = fma2_(LB[6], d2, l1); l1 = fma2_(LB[8], dd3, l1);
            l2 = mul2_(LB[2], d2); l2 = fma2_(LB[9], dd3, l2);
            l3 = mul2_(LB[3], dd3);
            u64 qB = fma2_(l1, l1, mul2_(l0, l0));
            qB = add2_(qB, fma2_(l3, l3, mul2_(l2, l2)));
            qB = mul2_(qB, NL2E2);
            float qa0, qa1, qb0, qb1;
            upk(qA, qa0, qa1); upk(qB, qb0, qb1);
            float acc = fmaf(wA0, ex2_(qa0), wA1 * ex2_(qa1))
                      + fmaf(wB0, ex2_(qb0), wB1 * ex2_(qb1));
            acc = red16_r4(acc);
            u_reg = fminf(fmaxf(acc, -10.f), 10.f);
            if (lane == 0) sm_u[(t + 1) & 1] = u_reg;
            BAR_ARRIVE_1();

            // get S_{t+1}, rebuild prep locally
            BAR_SYNC_2();
            const float* Sb = sm_S[(t + 1) & 1];
            const float s1v = Sb[i1], s2v = Sb[i2], s3v = Sb[i3];
            m0 = n0; m1 = n1; m2 = n2; m3 = n3;
            r1_ = sgn * s1v;
            const float r2 = sgn * s2v;
            r3_ = sgn * s3v;
            const float th = m2 + r2, thd = m3 + r3_;
            const float s = __sinf(th);
            c_ = __cosf(th);
            rd_ = rcp_(fmaf(-K2c * c_, c_, K3c));
            tks_ = ((thd * thd) * K1c) * s;
            g98_ = 9.8f * s;
        }
    } else {
        // ================= W0 loop: S-cycle =================
        #pragma unroll 1
        for (int t = 0; t < 60; ++t) {
            BAR_SYNC_1();
            const float u = sm_u[t & 1];

            const float ud = u * INV11c;
            const float temp = tks_ + ud;
            const float num = fmaf(-c_, temp, g98_);
            const float ta = num * rd_;
            const float xa = fmaf(-K1c, ta * c_, temp);
            const float y1 = fmaf(DTc, xa, r1_);
            const float y3 = fmaf(DTc, ta, r3_);

            // gather all 9 (y1,y3)
            u64 z[9];
            #pragma unroll
            for (int j = 0; j < 9; ++j) {
                const float g1 = __shfl_sync(0xffffffffu, y1, j);
                const float g3 = __shfl_sync(0xffffffffu, y3, j);
                z[j] = pk(g1, g3);
            }
            const u64 sA = add2_(add2_(z[1], z[2]), add2_(z[3], z[4]));
            const u64 sB = add2_(add2_(z[5], z[6]), add2_(z[7], z[8]));
            const u64 d13 = fma2_(WI_2, add2_(sA, sB), mul2_(W0_2, z[0]));
            float d1, d3; upk(d13, d1, d3);

            // linear-coordinate covariance entries (old S)
            const float A0 = fmaf(DTc, S10, S00);
            const float A1v = DTc * S11;
            const float C0 = fmaf(DTc, S30, S20);
            const float C1 = fmaf(DTc, S31, S21);
            const float C2v = fmaf(DTc, S32, S22);
            const float C3 = DTc * S33;
            const float c00 = fmaf(A1v, A1v, A0 * A0) + DIAG5c;
            const float c20 = fmaf(A1v, C1, A0 * C0);
            const float c22 = fmaf(C3, C3, fmaf(C2v, C2v, fmaf(C1, C1, C0 * C0))) + DIAG5c;
            const u64 A0h2 = sp2(0.5f * A0), A1h2 = sp2(0.5f * A1v);
            const u64 C0h2 = sp2(0.5f * C0), C1h2 = sp2(0.5f * C1);
            const u64 C2h2 = sp2(0.5f * C2v), C3h2 = sp2(0.5f * C3);

            // moments
            const u64 gz1 = fma2_(z[5], NM1_2, z[1]);
            const u64 gz2 = fma2_(z[6], NM1_2, z[2]);
            const u64 gz3 = fma2_(z[7], NM1_2, z[3]);
            const u64 gz4 = fma2_(z[8], NM1_2, z[4]);
            const u64 p1030 = fma2_(A1h2, gz2, mul2_(A0h2, gz1));
            u64 p2132 = fma2_(C1h2, gz2, mul2_(C0h2, gz1));
            p2132 = fma2_(C2h2, gz3, p2132);
            p2132 = fma2_(C3h2, gz4, p2132);
            float p10, p30, p21, p32;
            upk(p1030, p10, p30); upk(p2132, p21, p32);
            u64 sq = mul2_(z[1], z[1]);
            sq = fma2_(z[2], z[2], sq); sq = fma2_(z[3], z[3], sq);
            sq = fma2_(z[4], z[4], sq); sq = fma2_(z[5], z[5], sq);
            sq = fma2_(z[6], z[6], sq); sq = fma2_(z[7], z[7], sq);
            sq = fma2_(z[8], z[8], sq);
            const u64 p1133 = fma2_(HALF2, sq, mul2_(z[0], z[0]));
            float p11, p33; upk(p1133, p11, p33);
            float y1j[9], y3j[9];
            #pragma unroll
            for (int j = 0; j < 9; ++j) upk(z[j], y1j[j], y3j[j]);
            float xs = y1j[1] * y3j[1];
            xs = fmaf(y1j[2], y3j[2], xs); xs = fmaf(y1j[3], y3j[3], xs);
            xs = fmaf(y1j[4], y3j[4], xs); xs = fmaf(y1j[5], y3j[5], xs);
            xs = fmaf(y1j[6], y3j[6], xs); xs = fmaf(y1j[7], y3j[7], xs);
            xs = fmaf(y1j[8], y3j[8], xs);
            const float p13 = fmaf(0.5f, xs, y1j[0] * y3j[0]);

            const float n0 = fmaf(DTc, m1, m0);
            const float n2 = fmaf(DTc, m3, m2);
            const float n1 = m1 + d1;
            const float n3 = m3 + d3;
            const float f1 = 5.f * d1, f3 = 5.f * d3;
            const float c11 = fmaf(-f1, d1, p11) + DIAG5c;
            const float c31 = fmaf(-f1, d3, p13);
            const float c33 = fmaf(-f3, d3, p33) + DIAG5c;
            const float c10 = p10, c30 = p30, c21 = p21, c32 = p32;

            const float q = fmaf(n0, n0, fmaf(n1, n1, fmaf(10.f * n2, n2, n3 * n3)));
            const float tr = c00 + c11 + fmaf(10.f, c22, c33);
            reward -= fmaf(0.2f, tr, q);

            // Cholesky
            const float rr0 = rsqrtf(c00);
            S00 = c00 * rr0;
            S10 = c10 * rr0; S20 = c20 * rr0; S30 = c30 * rr0;
            const float a11 = fmaf(-S10, S10, c11);
            const float rr1 = rsqrtf(a11);
            S11 = a11 * rr1;
            S21 = fmaf(-S20, S10, c21) * rr1;
            S31 = fmaf(-S30, S10, c31) * rr1;
            const float a22 = fmaf(-S21, S21, fmaf(-S20, S20, c22));
            const float rr2 = rsqrtf(a22);
            S22 = a22 * rr2;
            S32 = fmaf(-S31, S21, fmaf(-S30, S20, c32)) * rr2;
            const float a33 = fmaf(-S32, S32, fmaf(-S31, S31, fmaf(-S30, S30, c33)));
            S33 = a33 * rsqrtf(a33);

            // publish S_{t+1}: ONE STS (lanes 0-10, slot 10 = 0)
            float sv = 0.f;
            if (lane == 0) sv = S00; else if (lane == 1) sv = S10;
            else if (lane == 2) sv = S20; else if (lane == 3) sv = S30;
            else if (lane == 4) sv = S11; else if (lane == 5) sv = S21;
            else if (lane == 6) sv = S31; else if (lane == 7) sv = S22;
            else if (lane == 8) sv = S32; else if (lane == 9) sv = S33;
            if (lane < 11) sm_S[(t + 1) & 1][lane] = sv;
            BAR_ARRIVE_2();

            // own prep for step t+1
            m0 = n0; m1 = n1; m2 = n2; m3 = n3;
            r0_ = sgn * (isC0 ? S00 : 0.f);
            r1_ = sgn * (isC0 ? S10 : (isC1 ? S11 : 0.f));
            const float r2n = sgn * (isC0 ? S20 : (isC1 ? S21 : (isC2 ? S22 : 0.f)));
            r3_ = sgn * (isC0 ? S30 : (isC1 ? S31 : (isC2 ? S32 : S33)));
            const float thn = m2 + r2n, thdn = m3 + r3_;
            const float sn = __sinf(thn);
            c_ = __cosf(thn);
            rd_ = rcp_(fmaf(-K2c * c_, c_, K3c));
            tks_ = ((thdn * thdn) * K1c) * sn;
            g98_ = 9.8f * sn;
        }
    }

    if (tid == 0) out[0] = reward;
}

extern "C" void kernel_launch(void* const* d_in, const int* in_sizes, int n_in,
                              void* d_out, int out_size) {
    (void)in_sizes; (void)n_in; (void)out_size;
    horizon_reward_kernel<<<1, 64>>>((const float*)d_in[0], (float*)d_out);
}

// round 13
// speedup vs baseline: 1.1722x; 1.1722x over previous
#include <cuda_runtime.h>
#include <math.h>

// HorizonReward — lean single-warp collapsed UT cartpole rollout (R13).
// Multi-warp splits (R11/R12) lose to barrier/handoff costs on the
// cross-warp S->prep->dyn dependence; single warp it is. This version is
// the minimal-slot fusion of all verified pieces:
//   - SIMT sigma points (lanes 0-8), one scalar dynamics chain per lane
//   - parallel shfl.idx gather of (y1,y3) AND swapped (y3,y1) packs ->
//     ALL moments packed f32x2 (no scalar p13 path)
//   - direct packed 2-chain policy (no affine-base machinery)
//   - radix-4 two-stage 16-lane policy reduction
//   - all S-only work (A/C coeffs, c00/c20/c22, packed consts, n0/n2)
//     hoisted into the post-Cholesky prep region
//   - x5-prescaled covariance so chol() yields sqrt(5)*S directly

typedef unsigned long long u64;

__device__ __forceinline__ u64 pk(float lo, float hi) {
    u64 r; asm("mov.b64 %0,{%1,%2};" : "=l"(r) : "f"(lo), "f"(hi)); return r;
}
__device__ __forceinline__ void upk(u64 a, float& x, float& y) {
    asm("mov.b64 {%0,%1},%2;" : "=f"(x), "=f"(y) : "l"(a));
}
__device__ __forceinline__ u64 sp2(float s) { return pk(s, s); }
__device__ __forceinline__ u64 fma2_(u64 a, u64 b, u64 c) {
    u64 d; asm("fma.rn.f32x2 %0,%1,%2,%3;" : "=l"(d) : "l"(a), "l"(b), "l"(c)); return d;
}
__device__ __forceinline__ u64 mul2_(u64 a, u64 b) {
    u64 d; asm("mul.rn.f32x2 %0,%1,%2;" : "=l"(d) : "l"(a), "l"(b)); return d;
}
__device__ __forceinline__ u64 add2_(u64 a, u64 b) {
    u64 d; asm("add.rn.f32x2 %0,%1,%2;" : "=l"(d) : "l"(a), "l"(b)); return d;
}
__device__ __forceinline__ float rcp_(float x) {
    float r; asm("rcp.approx.f32 %0,%1;" : "=f"(r) : "f"(x)); return r;
}
__device__ __forceinline__ float ex2_(float x) {
    float r; asm("ex2.approx.f32 %0,%1;" : "=f"(r) : "f"(x)); return r;
}
__device__ __forceinline__ float red16_r4(float x) {
    const float a = __shfl_xor_sync(0xffffffffu, x, 4);
    const float b = __shfl_xor_sync(0xffffffffu, x, 8);
    const float c = __shfl_xor_sync(0xffffffffu, x, 12);
    x = (x + a) + (b + c);
    const float d = __shfl_xor_sync(0xffffffffu, x, 1);
    const float e = __shfl_xor_sync(0xffffffffu, x, 2);
    const float f = __shfl_xor_sync(0xffffffffu, x, 3);
    return (x + d) + (e + f);
}

#define DTc      0.05f
#define K1c      (0.05f / 1.1f)
#define K3c      (0.5f * (4.0f / 3.0f))
#define K2c      (0.5f * 0.1f / 1.1f)
#define INV11c   (1.0f / 1.1f)
#define DIAG5c   (5.0f * (0.01f * 0.05f + 2.0f * 1e-6f))

// direct packed policy: chains A (RBFs jj, jj+16) and B (jj+32, jj+48 padded)
__device__ __forceinline__ float policy_eval(
    float n0, float n1, float n2, float n3,
    float wA0, float wA1, float wB0, float wB1,
    const u64* nmuA, const u64* LA, const u64* nmuB, const u64* LB,
    u64 NL2E2)
{
    const u64 s0 = sp2(n0), s1 = sp2(n1), s2 = sp2(n2), s3 = sp2(n3);
    u64 d0 = add2_(s0, nmuA[0]), d1 = add2_(s1, nmuA[1]);
    u64 d2 = add2_(s2, nmuA[2]), d3 = add2_(s3, nmuA[3]);
    u64 l0 = mul2_(LA[0], d0);
    l0 = fma2_(LA[4], d1, l0); l0 = fma2_(LA[5], d2, l0); l0 = fma2_(LA[7], d3, l0);
    u64 l1 = mul2_(LA[1], d1); l1 = fma2_(LA[6], d2, l1); l1 = fma2_(LA[8], d3, l1);
    u64 l2 = mul2_(LA[2], d2); l2 = fma2_(LA[9], d3, l2);
    u64 l3 = mul2_(LA[3], d3);
    u64 qA = fma2_(l1, l1, mul2_(l0, l0));
    qA = add2_(qA, fma2_(l3, l3, mul2_(l2, l2)));
    qA = mul2_(qA, NL2E2);
    d0 = add2_(s0, nmuB[0]); d1 = add2_(s1, nmuB[1]);
    d2 = add2_(s2, nmuB[2]); d3 = add2_(s3, nmuB[3]);
    l0 = mul2_(LB[0], d0);
    l0 = fma2_(LB[4], d1, l0); l0 = fma2_(LB[5], d2, l0); l0 = fma2_(LB[7], d3, l0);
    l1 = mul2_(LB[1], d1); l1 = fma2_(LB[6], d2, l1); l1 = fma2_(LB[8], d3, l1);
    l2 = mul2_(LB[2], d2); l2 = fma2_(LB[9], d3, l2);
    l3 = mul2_(LB[3], d3);
    u64 qB = fma2_(l1, l1, mul2_(l0, l0));
    qB = add2_(qB, fma2_(l3, l3, mul2_(l2, l2)));
    qB = mul2_(qB, NL2E2);
    float qa0, qa1, qb0, qb1;
    upk(qA, qa0, qa1); upk(qB, qb0, qb1);
    float acc = fmaf(wA0, ex2_(qa0), wA1 * ex2_(qa1))
              + fmaf(wB0, ex2_(qb0), wB1 * ex2_(qb1));
    acc = red16_r4(acc);
    return fminf(fmaxf(acc, -10.f), 10.f);
}

__global__ __launch_bounds__(32, 1)
void horizon_reward_kernel(const float* __restrict__ p, float* __restrict__ out)
{
    const int lane = threadIdx.x & 31;
    const int jj = lane & 15;

    // ---- policy params ----
    u64 nmuA[4], LA[10], nmuB[4], LB[10];
    float wA0, wA1, wB0, wB1;
    {
        const int a0 = jj, a1 = jj + 16, b0 = jj + 32, b1 = jj + 48;
        const bool hb1 = (b1 < 50);
        wA0 = p[a0]; wA1 = p[a1];
        wB0 = p[b0]; wB1 = hb1 ? p[b1] : 0.f;
        #pragma unroll
        for (int k = 0; k < 4; ++k) {
            nmuA[k] = pk(-p[50 + k * 50 + a0], -p[50 + k * 50 + a1]);
            nmuB[k] = pk(-p[50 + k * 50 + b0], hb1 ? -p[50 + k * 50 + b1] : 0.f);
        }
        #pragma unroll
        for (int t = 0; t < 10; ++t) {
            LA[t] = pk(p[250 + a0 * 10 + t], p[250 + a1 * 10 + t]);
            LB[t] = pk(p[250 + b0 * 10 + t], hb1 ? p[250 + b1 * 10 + t] : 0.f);
        }
    }

    const u64 NL2E2 = sp2(-1.4426950408889634f);
    const u64 NM1_2 = sp2(-1.f);
    const u64 W0_2 = sp2(0.2f), WI_2 = sp2(0.1f), HALF2 = sp2(0.5f);

    // ---- sigma-point roles ----
    const int pt = jj;
    const int col = (pt == 0) ? 3 : ((pt - 1) & 3);
    const float sgn = (pt >= 1 && pt <= 4) ? 1.f : ((pt >= 5 && pt <= 8) ? -1.f : 0.f);
    const bool isC0 = (col == 0), isC1 = (col == 1), isC2 = (col == 2);

    // ---- state ----
    float m0 = 0.f, m1 = 0.f, m2 = 0.1f, m3 = 0.f;
    const float r0i = 2.23606797749979f * 1e-3f;
    float S00 = r0i, S10 = 0.f, S20 = 0.f, S30 = 0.f;
    float S11 = r0i, S21 = 0.f, S31 = 0.f;
    float S22 = r0i, S32 = 0.f;
    float S33 = r0i;

    // ---- prep registers (filled from current S/m at end of each step) ----
    float r1_, r3_, tks_, g98_, c_, rd_;
    float c00_, c20_, c22_, n0p_, n2p_;
    u64 A0h2_, A1h2_, C0h2_, C1h2_, C2h2_, C3h2_;

    #define PREP_FROM_STATE()                                                 \
    {                                                                         \
        r1_ = sgn * (isC0 ? S10 : (isC1 ? S11 : 0.f));                        \
        const float r2p = sgn * (isC0 ? S20 : (isC1 ? S21 : (isC2 ? S22 : 0.f))); \
        r3_ = sgn * (isC0 ? S30 : (isC1 ? S31 : (isC2 ? S32 : S33)));         \
        const float thp = m2 + r2p, thdp = m3 + r3_;                          \
        const float sp = __sinf(thp);                                         \
        c_ = __cosf(thp);                                                     \
        rd_ = rcp_(fmaf(-K2c * c_, c_, K3c));                                 \
        tks_ = ((thdp * thdp) * K1c) * sp;                                    \
        g98_ = 9.8f * sp;                                                     \
        const float A0 = fmaf(DTc, S10, S00);                                 \
        const float A1v = DTc * S11;                                          \
        const float C0 = fmaf(DTc, S30, S20);                                 \
        const float C1 = fmaf(DTc, S31, S21);                                 \
        const float C2v = fmaf(DTc, S32, S22);                                \
        const float C3 = DTc * S33;                                           \
        c00_ = fmaf(A1v, A1v, A0 * A0) + DIAG5c;                              \
        c20_ = fmaf(A1v, C1, A0 * C0);                                        \
        c22_ = fmaf(C3, C3, fmaf(C2v, C2v, fmaf(C1, C1, C0 * C0))) + DIAG5c;  \
        A0h2_ = sp2(0.5f * A0); A1h2_ = sp2(0.5f * A1v);                      \
        C0h2_ = sp2(0.5f * C0); C1h2_ = sp2(0.5f * C1);                       \
        C2h2_ = sp2(0.5f * C2v); C3h2_ = sp2(0.5f * C3);                      \
        n0p_ = fmaf(DTc, m1, m0);                                             \
        n2p_ = fmaf(DTc, m3, m2);                                             \
    }

    PREP_FROM_STATE();

    float u = policy_eval(m0, m1, m2, m3, wA0, wA1, wB0, wB1,
                          nmuA, LA, nmuB, LB, NL2E2);
    float reward = 0.f;

    #pragma unroll 1
    for (int t = 0; t < 60; ++t) {
        // ---- post-u dynamics (one scalar chain per lane) ----
        const float ud = u * INV11c;
        const float temp = tks_ + ud;
        const float num = fmaf(-c_, temp, g98_);
        const float ta = num * rd_;
        const float xa = fmaf(-K1c, ta * c_, temp);
        const float y1 = fmaf(DTc, xa, r1_);      // next1 - m1 (uncentered)
        const float y3 = fmaf(DTc, ta, r3_);      // next3 - m3 (uncentered)

        // ---- gather z=(y1,y3) and swapped zs=(y3,y1): 18 parallel shfls ----
        u64 z[9], zs[9];
        #pragma unroll
        for (int j = 0; j < 9; ++j) {
            const float g1 = __shfl_sync(0xffffffffu, y1, j);
            const float g3 = __shfl_sync(0xffffffffu, y3, j);
            z[j] = pk(g1, g3);
            zs[j] = pk(g3, g1);
        }

        // ---- packed means ----
        const u64 sA = add2_(add2_(z[1], z[2]), add2_(z[3], z[4]));
        const u64 sB = add2_(add2_(z[5], z[6]), add2_(z[7], z[8]));
        const u64 d13 = fma2_(WI_2, add2_(sA, sB), mul2_(W0_2, z[0]));
        float d1, d3; upk(d13, d1, d3);

        const float n0 = n0p_;
        const float n2 = n2p_;
        const float n1 = m1 + d1;
        const float n3 = m3 + d3;

        // ---- next u (the loop-carried critical chain) ----
        const float u_next = policy_eval(n0, n1, n2, n3, wA0, wA1, wB0, wB1,
                                         nmuA, LA, nmuB, LB, NL2E2);

        // ---- packed moments (off the u-path) ----
        const u64 gz1 = fma2_(z[5], NM1_2, z[1]);
        const u64 gz2 = fma2_(z[6], NM1_2, z[2]);
        const u64 gz3 = fma2_(z[7], NM1_2, z[3]);
        const u64 gz4 = fma2_(z[8], NM1_2, z[4]);
        const u64 p1030 = fma2_(A1h2_, gz2, mul2_(A0h2_, gz1));
        u64 p2132 = fma2_(C1h2_, gz2, mul2_(C0h2_, gz1));
        p2132 = fma2_(C2h2_, gz3, p2132);
        p2132 = fma2_(C3h2_, gz4, p2132);
        float p10, p30, p21, p32;
        upk(p1030, p10, p30); upk(p2132, p21, p32);

        u64 sq = mul2_(z[1], z[1]);
        sq = fma2_(z[2], z[2], sq); sq = fma2_(z[3], z[3], sq);
        sq = fma2_(z[4], z[4], sq); sq = fma2_(z[5], z[5], sq);
        sq = fma2_(z[6], z[6], sq); sq = fma2_(z[7], z[7], sq);
        sq = fma2_(z[8], z[8], sq);
        const u64 p1133 = fma2_(HALF2, sq, mul2_(z[0], z[0]));
        float p11, p33; upk(p1133, p11, p33);

        u64 sq13 = mul2_(z[1], zs[1]);
        sq13 = fma2_(z[2], zs[2], sq13); sq13 = fma2_(z[3], zs[3], sq13);
        sq13 = fma2_(z[4], zs[4], sq13); sq13 = fma2_(z[5], zs[5], sq13);
        sq13 = fma2_(z[6], zs[6], sq13); sq13 = fma2_(z[7], zs[7], sq13);
        sq13 = fma2_(z[8], zs[8], sq13);
        const u64 p13p = fma2_(HALF2, sq13, mul2_(z[0], zs[0]));
        float p13, p13h; upk(p13p, p13, p13h);

        // ---- de-meaned covariance (x5 prescaled) ----
        const float f1 = 5.f * d1, f3 = 5.f * d3;
        const float c11 = fmaf(-f1, d1, p11) + DIAG5c;
        const float c31 = fmaf(-f1, d3, p13);
        const float c33 = fmaf(-f3, d3, p33) + DIAG5c;
        const float c00 = c00_, c20 = c20_, c22 = c22_;
        const float c10 = p10, c30 = p30, c21 = p21, c32 = p32;

        // ---- reward: n^T Q n + 0.2 * trace(Q * 5C) ----
        const float q = fmaf(n0, n0, fmaf(n1, n1, fmaf(10.f * n2, n2, n3 * n3)));
        const float tr = c00 + c11 + fmaf(10.f, c22, c33);
        reward -= fmaf(0.2f, tr, q);

        // ---- 4x4 Cholesky via rsqrt (output is sqrt(5)*S) ----
        const float rr0 = rsqrtf(c00);
        S00 = c00 * rr0;
        S10 = c10 * rr0; S20 = c20 * rr0; S30 = c30 * rr0;
        const float a11 = fmaf(-S10, S10, c11);
        const float rr1 = rsqrtf(a11);
        S11 = a11 * rr1;
        S21 = fmaf(-S20, S10, c21) * rr1;
        S31 = fmaf(-S30, S10, c31) * rr1;
        const float a22 = fmaf(-S21, S21, fmaf(-S20, S20, c22));
        const float rr2 = rsqrtf(a22);
        S22 = a22 * rr2;
        S32 = fmaf(-S31, S21, fmaf(-S30, S20, c32)) * rr2;
        const float a33 = fmaf(-S32, S32, fmaf(-S31, S31, fmaf(-S30, S30, c33)));
        S33 = a33 * rsqrtf(a33);

        // ---- state update + prep for next step ----
        m0 = n0; m1 = n1; m2 = n2; m3 = n3;
        PREP_FROM_STATE();

        u = u_next;
    }

    if (lane == 0) out[0] = reward;
}

extern "C" void kernel_launch(void* const* d_in, const int* in_sizes, int n_in,
                              void* d_out, int out_size) {
    (void)in_sizes; (void)n_in; (void)out_size;
    horizon_reward_kernel<<<1, 32>>>((const float*)d_in[0], (float*)d_out);
}

// round 14
// speedup vs baseline: 2.0533x; 1.7517x over previous
#include <cuda_runtime.h>
#include <math.h>

// HorizonReward — R14: 32-lane single-chain policy + gather moments.
// The ~650cyc/step floor == fma-pipe issue cycles (FFMA2 rt~4 => packing is
// cycle-neutral). Cut real FMA-equivalents: policy spread over 32 lanes
// (ONE packed chain per lane: RBFs lane, lane+32) instead of 16 lanes with
// two chains. Moments via R10's parallel shfl gather (cheap). Affine-l
// policy split retained (R13 showed it's load-bearing). Loop structure is
// R10's verified shape. x5-prescaled covariance -> chol gives sqrt(5)*S.

typedef unsigned long long u64;

__device__ __forceinline__ u64 pk(float lo, float hi) {
    u64 r; asm("mov.b64 %0,{%1,%2};" : "=l"(r) : "f"(lo), "f"(hi)); return r;
}
__device__ __forceinline__ void upk(u64 a, float& x, float& y) {
    asm("mov.b64 {%0,%1},%2;" : "=f"(x), "=f"(y) : "l"(a));
}
__device__ __forceinline__ u64 sp2(float s) { return pk(s, s); }
__device__ __forceinline__ u64 fma2_(u64 a, u64 b, u64 c) {
    u64 d; asm("fma.rn.f32x2 %0,%1,%2,%3;" : "=l"(d) : "l"(a), "l"(b), "l"(c)); return d;
}
__device__ __forceinline__ u64 mul2_(u64 a, u64 b) {
    u64 d; asm("mul.rn.f32x2 %0,%1,%2;" : "=l"(d) : "l"(a), "l"(b)); return d;
}
__device__ __forceinline__ u64 add2_(u64 a, u64 b) {
    u64 d; asm("add.rn.f32x2 %0,%1,%2;" : "=l"(d) : "l"(a), "l"(b)); return d;
}
__device__ __forceinline__ float rcp_(float x) {
    float r; asm("rcp.approx.f32 %0,%1;" : "=f"(r) : "f"(x)); return r;
}
__device__ __forceinline__ float ex2_(float x) {
    float r; asm("ex2.approx.f32 %0,%1;" : "=f"(r) : "f"(x)); return r;
}
// 3-stage mixed-radix 32-lane reduction: (16) then (4,8,12) then (1,2,3)
__device__ __forceinline__ float red32_m(float x) {
    x += __shfl_xor_sync(0xffffffffu, x, 16);
    const float a = __shfl_xor_sync(0xffffffffu, x, 4);
    const float b = __shfl_xor_sync(0xffffffffu, x, 8);
    const float c = __shfl_xor_sync(0xffffffffu, x, 12);
    x = (x + a) + (b + c);
    const float d = __shfl_xor_sync(0xffffffffu, x, 1);
    const float e = __shfl_xor_sync(0xffffffffu, x, 2);
    const float f = __shfl_xor_sync(0xffffffffu, x, 3);
    return (x + d) + (e + f);
}

#define DTc      0.05f
#define K1c      (0.05f / 1.1f)
#define K3c      (0.5f * (4.0f / 3.0f))
#define K2c      (0.5f * 0.1f / 1.1f)
#define INV11c   (1.0f / 1.1f)
#define DIAG5c   (5.0f * (0.01f * 0.05f + 2.0f * 1e-6f))

__global__ __launch_bounds__(32, 1)
void horizon_reward_kernel(const float* __restrict__ p, float* __restrict__ out)
{
    const int lane = threadIdx.x & 31;

    // ---- policy params: ONE packed chain per lane (RBFs lane, lane+32) ----
    u64 nmu[4], L[10];
    float w0p, w1p;
    {
        const int a0 = lane, a1 = lane + 32;
        const bool hb = (a1 < 50);
        w0p = p[a0]; w1p = hb ? p[a1] : 0.f;
        #pragma unroll
        for (int k = 0; k < 4; ++k)
            nmu[k] = pk(-p[50 + k * 50 + a0], hb ? -p[50 + k * 50 + a1] : 0.f);
        #pragma unroll
        for (int t = 0; t < 10; ++t)
            L[t] = pk(p[250 + a0 * 10 + t], hb ? p[250 + a1 * 10 + t] : 0.f);
    }

    const u64 NL2E2 = sp2(-1.4426950408889634f);
    const u64 NM1_2 = sp2(-1.f);
    const u64 W0_2 = sp2(0.2f), WI_2 = sp2(0.1f), HALF2 = sp2(0.5f);

    // ---- sigma-point roles: lanes 0-8 own points; 9-31 harmless center ----
    const int pt = lane;
    const int col = (pt == 0) ? 3 : ((pt - 1) & 3);
    const float sgn = (pt >= 1 && pt <= 4) ? 1.f : ((pt >= 5 && pt <= 8) ? -1.f : 0.f);
    const bool isC0 = (col == 0), isC1 = (col == 1), isC2 = (col == 2);

    // ---- state (warp-uniform) ----
    float m0 = 0.f, m1 = 0.f, m2 = 0.1f, m3 = 0.f;
    const float r0i = 2.23606797749979f * 1e-3f;
    float S00 = r0i, S10 = 0.f, S20 = 0.f, S30 = 0.f;
    float S11 = r0i, S21 = 0.f, S31 = 0.f;
    float S22 = r0i, S32 = 0.f;
    float S33 = r0i;

    // ---- initial u = policy(m) ----
    float u;
    {
        u64 d0 = add2_(sp2(m0), nmu[0]), d1 = add2_(sp2(m1), nmu[1]);
        u64 d2 = add2_(sp2(m2), nmu[2]), d3 = add2_(sp2(m3), nmu[3]);
        u64 l0 = mul2_(L[0], d0);
        l0 = fma2_(L[4], d1, l0); l0 = fma2_(L[5], d2, l0); l0 = fma2_(L[7], d3, l0);
        u64 l1 = mul2_(L[1], d1); l1 = fma2_(L[6], d2, l1); l1 = fma2_(L[8], d3, l1);
        u64 l2 = mul2_(L[2], d2); l2 = fma2_(L[9], d3, l2);
        u64 l3 = mul2_(L[3], d3);
        u64 q = fma2_(l1, l1, mul2_(l0, l0));
        q = add2_(q, fma2_(l3, l3, mul2_(l2, l2)));
        q = mul2_(q, NL2E2);
        float qa, qb; upk(q, qa, qb);
        float acc = fmaf(w0p, ex2_(qa), w1p * ex2_(qb));
        acc = red32_m(acc);
        u = fminf(fmaxf(acc, -10.f), 10.f);
    }

    float reward = 0.f;

    #pragma unroll 1
    for (int t = 0; t < 60; ++t) {
        // ======== S-dependent pre-u work ========
        const float r1 = sgn * (isC0 ? S10 : (isC1 ? S11 : 0.f));
        const float r2 = sgn * (isC0 ? S20 : (isC1 ? S21 : (isC2 ? S22 : 0.f)));
        const float r3 = sgn * (isC0 ? S30 : (isC1 ? S31 : (isC2 ? S32 : S33)));

        const float th = m2 + r2, thd = m3 + r3;
        const float s = __sinf(th), c = __cosf(th);
        const float rd = rcp_(fmaf(-K2c * c, c, K3c));
        const float tks = ((thd * thd) * K1c) * s;
        const float g98 = 9.8f * s;

        const float n0 = fmaf(DTc, m1, m0);
        const float n2 = fmaf(DTc, m3, m2);

        // analytic linear-coordinate covariance entries (exact)
        const float A0 = fmaf(DTc, S10, S00);
        const float A1v = DTc * S11;
        const float C0 = fmaf(DTc, S30, S20);
        const float C1 = fmaf(DTc, S31, S21);
        const float C2v = fmaf(DTc, S32, S22);
        const float C3 = DTc * S33;
        const float c00 = fmaf(A1v, A1v, A0 * A0) + DIAG5c;
        const float c20 = fmaf(A1v, C1, A0 * C0);
        const float c22 = fmaf(C3, C3, fmaf(C2v, C2v, fmaf(C1, C1, C0 * C0))) + DIAG5c;
        const u64 A0h2 = sp2(0.5f * A0), A1h2 = sp2(0.5f * A1v);
        const u64 C0h2 = sp2(0.5f * C0), C1h2 = sp2(0.5f * C1);
        const u64 C2h2 = sp2(0.5f * C2v), C3h2 = sp2(0.5f * C3);

        // ---- policy l-vector BASES at (n0, m1, n2, m3) ----
        const u64 a0c = add2_(sp2(n0), nmu[0]), a1m = add2_(sp2(m1), nmu[1]);
        const u64 a2c = add2_(sp2(n2), nmu[2]), a3m = add2_(sp2(m3), nmu[3]);
        u64 l0b = mul2_(L[0], a0c);
        l0b = fma2_(L[4], a1m, l0b); l0b = fma2_(L[5], a2c, l0b); l0b = fma2_(L[7], a3m, l0b);
        u64 l1b = mul2_(L[1], a1m); l1b = fma2_(L[6], a2c, l1b); l1b = fma2_(L[8], a3m, l1b);
        u64 l2b = mul2_(L[2], a2c); l2b = fma2_(L[9], a3m, l2b);
        u64 l3b = mul2_(L[3], a3m);

        // ================== u arrives: short post-u chain ====================
        const float ud = u * INV11c;
        const float temp = tks + ud;
        const float num = fmaf(-c, temp, g98);
        const float ta = num * rd;
        const float xa = fmaf(-K1c, ta * c, temp);
        const float y1 = fmaf(DTc, xa, r1);      // next1 - m1 (uncentered)
        const float y3 = fmaf(DTc, ta, r3);      // next3 - m3 (uncentered)

        // ---- gather all 9 (y1,y3): 18 parallel shfl.idx ----
        u64 z[9];
        #pragma unroll
        for (int j = 0; j < 9; ++j) {
            const float g1 = __shfl_sync(0xffffffffu, y1, j);
            const float g3 = __shfl_sync(0xffffffffu, y3, j);
            z[j] = pk(g1, g3);
        }

        // ---- packed means ----
        const u64 sA = add2_(add2_(z[1], z[2]), add2_(z[3], z[4]));
        const u64 sB = add2_(add2_(z[5], z[6]), add2_(z[7], z[8]));
        const u64 d13 = fma2_(WI_2, add2_(sA, sB), mul2_(W0_2, z[0]));
        float d1, d3; upk(d13, d1, d3);

        // ---- policy fixup + reduce -> u_{t+1} ----
        {
            const u64 d1_2 = sp2(d1), d3_2 = sp2(d3);
            u64 l0 = fma2_(L[4], d1_2, fma2_(L[7], d3_2, l0b));
            u64 l1 = fma2_(L[1], d1_2, fma2_(L[8], d3_2, l1b));
            u64 l2 = fma2_(L[9], d3_2, l2b);
            u64 l3 = fma2_(L[3], d3_2, l3b);
            u64 q = fma2_(l1, l1, mul2_(l0, l0));
            q = add2_(q, fma2_(l3, l3, mul2_(l2, l2)));
            q = mul2_(q, NL2E2);
            float qa, qb; upk(q, qa, qb);
            float acc = fmaf(w0p, ex2_(qa), w1p * ex2_(qb));
            acc = red32_m(acc);
            u = fminf(fmaxf(acc, -10.f), 10.f);
        }

        // ---- moments from gathered z (off the u-path) ----
        const u64 gz1 = fma2_(z[5], NM1_2, z[1]);
        const u64 gz2 = fma2_(z[6], NM1_2, z[2]);
        const u64 gz3 = fma2_(z[7], NM1_2, z[3]);
        const u64 gz4 = fma2_(z[8], NM1_2, z[4]);
        const u64 p1030 = fma2_(A1h2, gz2, mul2_(A0h2, gz1));
        u64 p2132 = fma2_(C1h2, gz2, mul2_(C0h2, gz1));
        p2132 = fma2_(C2h2, gz3, p2132);
        p2132 = fma2_(C3h2, gz4, p2132);
        float p10, p30, p21, p32;
        upk(p1030, p10, p30); upk(p2132, p21, p32);
        u64 sq = mul2_(z[1], z[1]);
        sq = fma2_(z[2], z[2], sq); sq = fma2_(z[3], z[3], sq);
        sq = fma2_(z[4], z[4], sq); sq = fma2_(z[5], z[5], sq);
        sq = fma2_(z[6], z[6], sq); sq = fma2_(z[7], z[7], sq);
        sq = fma2_(z[8], z[8], sq);
        const u64 p1133 = fma2_(HALF2, sq, mul2_(z[0], z[0]));
        float p11, p33; upk(p1133, p11, p33);
        float y1j[9], y3j[9];
        #pragma unroll
        for (int j = 0; j < 9; ++j) upk(z[j], y1j[j], y3j[j]);
        float xs = y1j[1] * y3j[1];
        xs = fmaf(y1j[2], y3j[2], xs); xs = fmaf(y1j[3], y3j[3], xs);
        xs = fmaf(y1j[4], y3j[4], xs); xs = fmaf(y1j[5], y3j[5], xs);
        xs = fmaf(y1j[6], y3j[6], xs); xs = fmaf(y1j[7], y3j[7], xs);
        xs = fmaf(y1j[8], y3j[8], xs);
        const float p13 = fmaf(0.5f, xs, y1j[0] * y3j[0]);

        // ---- de-meaned covariance + next mean ----
        const float n1 = m1 + d1;
        const float n3 = m3 + d3;
        const float f1 = 5.f * d1, f3 = 5.f * d3;
        const float c11 = fmaf(-f1, d1, p11) + DIAG5c;
        const float c31 = fmaf(-f1, d3, p13);
        const float c33 = fmaf(-f3, d3, p33) + DIAG5c;
        const float c10 = p10, c30 = p30, c21 = p21, c32 = p32;

        // ---- reward: n^T Q n + 0.2 * trace(Q * 5C) ----
        const float q = fmaf(n0, n0, fmaf(n1, n1, fmaf(10.f * n2, n2, n3 * n3)));
        const float tr = c00 + c11 + fmaf(10.f, c22, c33);
        reward -= fmaf(0.2f, tr, q);

        // ---- 4x4 Cholesky via rsqrt (output is sqrt(5)*S) ----
        const float rr0 = rsqrtf(c00);
        S00 = c00 * rr0;
        S10 = c10 * rr0; S20 = c20 * rr0; S30 = c30 * rr0;
        const float a11 = fmaf(-S10, S10, c11);
        const float rr1 = rsqrtf(a11);
        S11 = a11 * rr1;
        S21 = fmaf(-S20, S10, c21) * rr1;
        S31 = fmaf(-S30, S10, c31) * rr1;
        const float a22 = fmaf(-S21, S21, fmaf(-S20, S20, c22));
        const float rr2 = rsqrtf(a22);
        S22 = a22 * rr2;
        S32 = fmaf(-S31, S21, fmaf(-S30, S20, c32)) * rr2;
        const float a33 = fmaf(-S32, S32, fmaf(-S31, S31, fmaf(-S30, S30, c33)));
        S33 = a33 * rsqrtf(a33);

        m0 = n0; m1 = n1; m2 = n2; m3 = n3;
    }

    if (lane == 0) out[0] = reward;
}

extern "C" void kernel_launch(void* const* d_in, const int* in_sizes, int n_in,
                              void* d_out, int out_size) {
    (void)in_sizes; (void)n_in; (void)out_size;
    horizon_reward_kernel<<<1, 32>>>((const float*)d_in[0], (float*)d_out);
}

// round 16
// speedup vs baseline: 2.1024x; 1.0239x over previous
#include <cuda_runtime.h>
#include <math.h>

// HorizonReward — R15 (resubmit; R15 bench was an infra failure, kernel
// never ran): R14 winner + slot/latency trims.
//   - scalar gather values (g1/g3) kept live: no re-unpack MOVs for p13
//   - p13 scalar (rt2 beats packed rt4)
//   - #pragma unroll 2: cross-iteration scheduling (moments/chol tail of
//     iter t overlaps prep/bases of iter t+1)
// Core structure (verified R14): 32-lane single-chain packed policy
// (RBFs lane, lane+32), affine-l bases, parallel shfl gather moments,
// analytic linear-coordinate covariance, x5-prescaled Cholesky.

typedef unsigned long long u64;

__device__ __forceinline__ u64 pk(float lo, float hi) {
    u64 r; asm("mov.b64 %0,{%1,%2};" : "=l"(r) : "f"(lo), "f"(hi)); return r;
}
__device__ __forceinline__ void upk(u64 a, float& x, float& y) {
    asm("mov.b64 {%0,%1},%2;" : "=f"(x), "=f"(y) : "l"(a));
}
__device__ __forceinline__ u64 sp2(float s) { return pk(s, s); }
__device__ __forceinline__ u64 fma2_(u64 a, u64 b, u64 c) {
    u64 d; asm("fma.rn.f32x2 %0,%1,%2,%3;" : "=l"(d) : "l"(a), "l"(b), "l"(c)); return d;
}
__device__ __forceinline__ u64 mul2_(u64 a, u64 b) {
    u64 d; asm("mul.rn.f32x2 %0,%1,%2;" : "=l"(d) : "l"(a), "l"(b)); return d;
}
__device__ __forceinline__ u64 add2_(u64 a, u64 b) {
    u64 d; asm("add.rn.f32x2 %0,%1,%2;" : "=l"(d) : "l"(a), "l"(b)); return d;
}
__device__ __forceinline__ float rcp_(float x) {
    float r; asm("rcp.approx.f32 %0,%1;" : "=f"(r) : "f"(x)); return r;
}
__device__ __forceinline__ float ex2_(float x) {
    float r; asm("ex2.approx.f32 %0,%1;" : "=f"(r) : "f"(x)); return r;
}
// 3-stage mixed-radix 32-lane reduction
__device__ __forceinline__ float red32_m(float x) {
    x += __shfl_xor_sync(0xffffffffu, x, 16);
    const float a = __shfl_xor_sync(0xffffffffu, x, 4);
    const float b = __shfl_xor_sync(0xffffffffu, x, 8);
    const float c = __shfl_xor_sync(0xffffffffu, x, 12);
    x = (x + a) + (b + c);
    const float d = __shfl_xor_sync(0xffffffffu, x, 1);
    const float e = __shfl_xor_sync(0xffffffffu, x, 2);
    const float f = __shfl_xor_sync(0xffffffffu, x, 3);
    return (x + d) + (e + f);
}

#define DTc      0.05f
#define K1c      (0.05f / 1.1f)
#define K3c      (0.5f * (4.0f / 3.0f))
#define K2c      (0.5f * 0.1f / 1.1f)
#define INV11c   (1.0f / 1.1f)
#define DIAG5c   (5.0f * (0.01f * 0.05f + 2.0f * 1e-6f))

__global__ __launch_bounds__(32, 1)
void horizon_reward_kernel(const float* __restrict__ p, float* __restrict__ out)
{
    const int lane = threadIdx.x & 31;

    // ---- policy params: ONE packed chain per lane (RBFs lane, lane+32) ----
    u64 nmu[4], L[10];
    float w0p, w1p;
    {
        const int a0 = lane, a1 = lane + 32;
        const bool hb = (a1 < 50);
        w0p = p[a0]; w1p = hb ? p[a1] : 0.f;
        #pragma unroll
        for (int k = 0; k < 4; ++k)
            nmu[k] = pk(-p[50 + k * 50 + a0], hb ? -p[50 + k * 50 + a1] : 0.f);
        #pragma unroll
        for (int t = 0; t < 10; ++t)
            L[t] = pk(p[250 + a0 * 10 + t], hb ? p[250 + a1 * 10 + t] : 0.f);
    }

    const u64 NL2E2 = sp2(-1.4426950408889634f);
    const u64 NM1_2 = sp2(-1.f);
    const u64 W0_2 = sp2(0.2f), WI_2 = sp2(0.1f), HALF2 = sp2(0.5f);

    // ---- sigma-point roles: lanes 0-8 own points; 9-31 harmless center ----
    const int pt = lane;
    const int col = (pt == 0) ? 3 : ((pt - 1) & 3);
    const float sgn = (pt >= 1 && pt <= 4) ? 1.f : ((pt >= 5 && pt <= 8) ? -1.f : 0.f);
    const bool isC0 = (col == 0), isC1 = (col == 1), isC2 = (col == 2);

    // ---- state (warp-uniform) ----
    float m0 = 0.f, m1 = 0.f, m2 = 0.1f, m3 = 0.f;
    const float r0i = 2.23606797749979f * 1e-3f;
    float S00 = r0i, S10 = 0.f, S20 = 0.f, S30 = 0.f;
    float S11 = r0i, S21 = 0.f, S31 = 0.f;
    float S22 = r0i, S32 = 0.f;
    float S33 = r0i;

    // ---- initial u = policy(m) ----
    float u;
    {
        u64 d0 = add2_(sp2(m0), nmu[0]), d1 = add2_(sp2(m1), nmu[1]);
        u64 d2 = add2_(sp2(m2), nmu[2]), d3 = add2_(sp2(m3), nmu[3]);
        u64 l0 = mul2_(L[0], d0);
        l0 = fma2_(L[4], d1, l0); l0 = fma2_(L[5], d2, l0); l0 = fma2_(L[7], d3, l0);
        u64 l1 = mul2_(L[1], d1); l1 = fma2_(L[6], d2, l1); l1 = fma2_(L[8], d3, l1);
        u64 l2 = mul2_(L[2], d2); l2 = fma2_(L[9], d3, l2);
        u64 l3 = mul2_(L[3], d3);
        u64 q = fma2_(l1, l1, mul2_(l0, l0));
        q = add2_(q, fma2_(l3, l3, mul2_(l2, l2)));
        q = mul2_(q, NL2E2);
        float qa, qb; upk(q, qa, qb);
        float acc = fmaf(w0p, ex2_(qa), w1p * ex2_(qb));
        acc = red32_m(acc);
        u = fminf(fmaxf(acc, -10.f), 10.f);
    }

    float reward = 0.f;

    #pragma unroll 2
    for (int t = 0; t < 60; ++t) {
        // ======== S-dependent pre-u work ========
        const float r1 = sgn * (isC0 ? S10 : (isC1 ? S11 : 0.f));
        const float r2 = sgn * (isC0 ? S20 : (isC1 ? S21 : (isC2 ? S22 : 0.f)));
        const float r3 = sgn * (isC0 ? S30 : (isC1 ? S31 : (isC2 ? S32 : S33)));

        const float th = m2 + r2, thd = m3 + r3;
        const float s = __sinf(th), c = __cosf(th);
        const float rd = rcp_(fmaf(-K2c * c, c, K3c));
        const float tks = ((thd * thd) * K1c) * s;
        const float g98 = 9.8f * s;

        const float n0 = fmaf(DTc, m1, m0);
        const float n2 = fmaf(DTc, m3, m2);

        // analytic linear-coordinate covariance entries (exact)
        const float A0 = fmaf(DTc, S10, S00);
        const float A1v = DTc * S11;
        const float C0 = fmaf(DTc, S30, S20);
        const float C1 = fmaf(DTc, S31, S21);
        const float C2v = fmaf(DTc, S32, S22);
        const float C3 = DTc * S33;
        const float c00 = fmaf(A1v, A1v, A0 * A0) + DIAG5c;
        const float c20 = fmaf(A1v, C1, A0 * C0);
        const float c22 = fmaf(C3, C3, fmaf(C2v, C2v, fmaf(C1, C1, C0 * C0))) + DIAG5c;
        const u64 A0h2 = sp2(0.5f * A0), A1h2 = sp2(0.5f * A1v);
        const u64 C0h2 = sp2(0.5f * C0), C1h2 = sp2(0.5f * C1);
        const u64 C2h2 = sp2(0.5f * C2v), C3h2 = sp2(0.5f * C3);

        // ---- policy l-vector BASES at (n0, m1, n2, m3) ----
        const u64 a0c = add2_(sp2(n0), nmu[0]), a1m = add2_(sp2(m1), nmu[1]);
        const u64 a2c = add2_(sp2(n2), nmu[2]), a3m = add2_(sp2(m3), nmu[3]);
        u64 l0b = mul2_(L[0], a0c);
        l0b = fma2_(L[4], a1m, l0b); l0b = fma2_(L[5], a2c, l0b); l0b = fma2_(L[7], a3m, l0b);
        u64 l1b = mul2_(L[1], a1m); l1b = fma2_(L[6], a2c, l1b); l1b = fma2_(L[8], a3m, l1b);
        u64 l2b = mul2_(L[2], a2c); l2b = fma2_(L[9], a3m, l2b);
        u64 l3b = mul2_(L[3], a3m);

        // ================== u arrives: short post-u chain ====================
        const float ud = u * INV11c;
        const float temp = tks + ud;
        const float num = fmaf(-c, temp, g98);
        const float ta = num * rd;
        const float xa = fmaf(-K1c, ta * c, temp);
        const float y1 = fmaf(DTc, xa, r1);      // next1 - m1 (uncentered)
        const float y3 = fmaf(DTc, ta, r3);      // next3 - m3 (uncentered)

        // ---- gather all 9 (y1,y3): 18 parallel shfl.idx; keep scalars live ----
        float g1[9], g3[9];
        u64 z[9];
        #pragma unroll
        for (int j = 0; j < 9; ++j) {
            g1[j] = __shfl_sync(0xffffffffu, y1, j);
            g3[j] = __shfl_sync(0xffffffffu, y3, j);
            z[j] = pk(g1[j], g3[j]);
        }

        // ---- packed means ----
        const u64 sA = add2_(add2_(z[1], z[2]), add2_(z[3], z[4]));
        const u64 sB = add2_(add2_(z[5], z[6]), add2_(z[7], z[8]));
        const u64 d13 = fma2_(WI_2, add2_(sA, sB), mul2_(W0_2, z[0]));
        float d1, d3; upk(d13, d1, d3);

        // ---- policy fixup + reduce -> u_{t+1} ----
        {
            const u64 d1_2 = sp2(d1), d3_2 = sp2(d3);
            u64 l0 = fma2_(L[4], d1_2, fma2_(L[7], d3_2, l0b));
            u64 l1 = fma2_(L[1], d1_2, fma2_(L[8], d3_2, l1b));
            u64 l2 = fma2_(L[9], d3_2, l2b);
            u64 l3 = fma2_(L[3], d3_2, l3b);
            u64 q = fma2_(l1, l1, mul2_(l0, l0));
            q = add2_(q, fma2_(l3, l3, mul2_(l2, l2)));
            q = mul2_(q, NL2E2);
            float qa, qb; upk(q, qa, qb);
            float acc = fmaf(w0p, ex2_(qa), w1p * ex2_(qb));
            acc = red32_m(acc);
            u = fminf(fmaxf(acc, -10.f), 10.f);
        }

        // ---- moments from gathered z (off the u-path) ----
        const u64 gz1 = fma2_(z[5], NM1_2, z[1]);
        const u64 gz2 = fma2_(z[6], NM1_2, z[2]);
        const u64 gz3 = fma2_(z[7], NM1_2, z[3]);
        const u64 gz4 = fma2_(z[8], NM1_2, z[4]);
        const u64 p1030 = fma2_(A1h2, gz2, mul2_(A0h2, gz1));
        u64 p2132 = fma2_(C1h2, gz2, mul2_(C0h2, gz1));
        p2132 = fma2_(C2h2, gz3, p2132);
        p2132 = fma2_(C3h2, gz4, p2132);
        float p10, p30, p21, p32;
        upk(p1030, p10, p30); upk(p2132, p21, p32);
        u64 sq = mul2_(z[1], z[1]);
        sq = fma2_(z[2], z[2], sq); sq = fma2_(z[3], z[3], sq);
        sq = fma2_(z[4], z[4], sq); sq = fma2_(z[5], z[5], sq);
        sq = fma2_(z[6], z[6], sq); sq = fma2_(z[7], z[7], sq);
        sq = fma2_(z[8], z[8], sq);
        const u64 p1133 = fma2_(HALF2, sq, mul2_(z[0], z[0]));
        float p11, p33; upk(p1133, p11, p33);
        // scalar p13 straight from the gather scalars (no re-unpack)
        float xs = g1[1] * g3[1];
        xs = fmaf(g1[2], g3[2], xs); xs = fmaf(g1[3], g3[3], xs);
        xs = fmaf(g1[4], g3[4], xs); xs = fmaf(g1[5], g3[5], xs);
        xs = fmaf(g1[6], g3[6], xs); xs = fmaf(g1[7], g3[7], xs);
        xs = fmaf(g1[8], g3[8], xs);
        const float p13 = fmaf(0.5f, xs, g1[0] * g3[0]);

        // ---- de-meaned covariance + next mean ----
        const float n1 = m1 + d1;
        const float n3 = m3 + d3;
        const float f1 = 5.f * d1, f3 = 5.f * d3;
        const float c11 = fmaf(-f1, d1, p11) + DIAG5c;
        const float c31 = fmaf(-f1, d3, p13);
        const float c33 = fmaf(-f3, d3, p33) + DIAG5c;
        const float c10 = p10, c30 = p30, c21 = p21, c32 = p32;

        // ---- reward: n^T Q n + 0.2 * trace(Q * 5C) ----
        const float q = fmaf(n0, n0, fmaf(n1, n1, fmaf(10.f * n2, n2, n3 * n3)));
        const float tr = c00 + c11 + fmaf(10.f, c22, c33);
        reward -= fmaf(0.2f, tr, q);

        // ---- 4x4 Cholesky via rsqrt (output is sqrt(5)*S) ----
        const float rr0 = rsqrtf(c00);
        S00 = c00 * rr0;
        S10 = c10 * rr0; S20 = c20 * rr0; S30 = c30 * rr0;
        const float a11 = fmaf(-S10, S10, c11);
        const float rr1 = rsqrtf(a11);
        S11 = a11 * rr1;
        S21 = fmaf(-S20, S10, c21) * rr1;
        S31 = fmaf(-S30, S10, c31) * rr1;
        const float a22 = fmaf(-S21, S21, fmaf(-S20, S20, c22));
        const float rr2 = rsqrtf(a22);
        S22 = a22 * rr2;
        S32 = fmaf(-S31, S21, fmaf(-S30, S20, c32)) * rr2;
        const float a33 = fmaf(-S32, S32, fmaf(-S31, S31, fmaf(-S30, S30, c33)));
        S33 = a33 * rsqrtf(a33);

        m0 = n0; m1 = n1; m2 = n2; m3 = n3;
    }

    if (lane == 0) out[0] = reward;
}

extern "C" void kernel_launch(void* const* d_in, const int* in_sizes, int n_in,
                              void* d_out, int out_size) {
    (void)in_sizes; (void)n_in; (void)out_size;
    horizon_reward_kernel<<<1, 32>>>((const float*)d_in[0], (float*)d_out);
}